// round 7
// baseline (speedup 1.0000x reference)
#include <cuda_runtime.h>
#include <cuda_bf16.h>
#include <math.h>

// Problem constants (fixed by the dataset: N=8192, D=512)
#define NROWS 8192
#define DDIM  512
#define MARGIN 0.3f

#define BM 128
#define BN 128
#define BK 16
#define NB (NROWS / BM)          // 64 block tiles per dimension
#define NTRI (NB * (NB + 1) / 2) // 2080 triangular block tiles

// ---------------- device scratch (static: no allocation allowed) ----------
__device__ float    g_normE[NROWS * DDIM];   // normalized embeddings (16 MB)
__device__ unsigned g_minposKey[NROWS];      // order-preserving uint of min positive g
__device__ unsigned g_maxnegKey[NROWS];      // order-preserving uint of max negative g
__device__ int      g_labels[NROWS];
__device__ int      g_labIs32;               // 1 if labels are int32, 0 if int64

// Order-preserving float<->uint encoding (monotone: f1<f2 <=> enc(f1)<enc(f2))
__device__ __forceinline__ unsigned fenc(float f) {
    unsigned u = __float_as_uint(f);
    return (u & 0x80000000u) ? ~u : (u | 0x80000000u);
}
__device__ __forceinline__ float fdec(unsigned k) {
    return (k & 0x80000000u) ? __uint_as_float(k & 0x7FFFFFFFu)
                             : __uint_as_float(~k);
}

#define MINPOS_INIT 0xFFFFFFFFu
#define MAXNEG_INIT 0x00000000u

// ---------------- kernel 0: detect labels dtype ---------------------------
// If the buffer is int64 (little-endian, labels < 2^31), every odd int32 word
// is zero. If int32, odd words are uniform labels in [0,1024): OR != 0 whp.
__global__ void detect_labels_kernel(const int* __restrict__ lab32) {
    __shared__ int sOr[256];
    int acc = 0;
    for (int i = threadIdx.x; i < NROWS / 2; i += 256)
        acc |= lab32[2 * i + 1];
    sOr[threadIdx.x] = acc;
    __syncthreads();
    #pragma unroll
    for (int st = 128; st; st >>= 1) {
        if (threadIdx.x < st) sOr[threadIdx.x] |= sOr[threadIdx.x + st];
        __syncthreads();
    }
    if (threadIdx.x == 0) g_labIs32 = (sOr[0] != 0) ? 1 : 0;
}

// ---------------- kernel 1: init scratch + convert labels ----------------
__global__ void init_kernel(const int* __restrict__ lab32) {
    int i = blockIdx.x * blockDim.x + threadIdx.x;
    if (i < NROWS) {
        g_minposKey[i] = MINPOS_INIT;
        g_maxnegKey[i] = MAXNEG_INIT;
        // int32 layout: lab32[i]; int64 layout: low word at lab32[2*i]
        g_labels[i] = g_labIs32 ? lab32[i] : lab32[2 * i];
    }
}

// ---------------- kernel 2: L2-normalize rows ----------------------------
__global__ void normalize_kernel(const float* __restrict__ emb) {
    int r = blockIdx.x;                  // one row per block, 128 threads
    const float4* src = (const float4*)(emb + (size_t)r * DDIM);
    float4 v = src[threadIdx.x];
    float s = v.x * v.x + v.y * v.y + v.z * v.z + v.w * v.w;
    #pragma unroll
    for (int o = 16; o; o >>= 1) s += __shfl_xor_sync(0xffffffffu, s, o);
    __shared__ float ws[4];
    if ((threadIdx.x & 31) == 0) ws[threadIdx.x >> 5] = s;
    __syncthreads();
    float tot = ws[0] + ws[1] + ws[2] + ws[3];
    float inv = rsqrtf(tot);
    float4 o4 = make_float4(v.x * inv, v.y * inv, v.z * inv, v.w * inv);
    ((float4*)(g_normE + (size_t)r * DDIM))[threadIdx.x] = o4;
}

// ---------------- kernel 3: fused symmetric Gram + masked min/max --------
// Triangular grid of 128x128 tiles; each tile feeds row-wise AND column-wise
// reductions (min/max is idempotent so diagonal double-processing is safe).
__device__ __forceinline__ int tri_off(int x) { return x * NB - x * (x - 1) / 2; }

__global__ void __launch_bounds__(256, 2) gram_kernel() {
    __shared__ float As[2][BK][BM];
    __shared__ float Bs[2][BK][BN];
    __shared__ int   sLabI[BM];
    __shared__ int   sLabJ[BN];
    __shared__ float sColMin[16][BN];
    __shared__ float sColMax[16][BN];

    // decode triangular block index -> (bi, bj), bi <= bj
    int b  = blockIdx.x;
    int bi = (int)floorf((129.0f - sqrtf(16641.0f - 8.0f * (float)b)) * 0.5f);
    while (tri_off(bi + 1) <= b) ++bi;
    while (tri_off(bi) > b)      --bi;
    int bj = bi + (b - tri_off(bi));

    const int rowBase = bi * BM;
    const int colBase = bj * BN;

    const int tid = threadIdx.x;
    const int tx  = tid & 15;   // 16 thread-cols
    const int ty  = tid >> 4;   // 16 thread-rows

    if (tid < BM)            sLabI[tid]       = g_labels[rowBase + tid];
    else                     sLabJ[tid - BM]  = g_labels[colBase + tid - BM];

    float acc[8][8];
    #pragma unroll
    for (int i = 0; i < 8; i++)
        #pragma unroll
        for (int j = 0; j < 8; j++) acc[i][j] = 0.0f;

    // global-load staging registers (4 x float4 per slab)
    float4 ra0, ra1, rb0, rb1;
    const int r0 = tid >> 2;              // 0..63
    const int c0 = (tid & 3) * 4;         // 0,4,8,12
    const int r1 = r0 + 64;

    const float* Abase = g_normE + (size_t)(rowBase) * DDIM;
    const float* Bbase = g_normE + (size_t)(colBase) * DDIM;

    // prologue: slab 0
    {
        const int k0 = 0;
        ra0 = *(const float4*)(Abase + (size_t)r0 * DDIM + k0 + c0);
        ra1 = *(const float4*)(Abase + (size_t)r1 * DDIM + k0 + c0);
        rb0 = *(const float4*)(Bbase + (size_t)r0 * DDIM + k0 + c0);
        rb1 = *(const float4*)(Bbase + (size_t)r1 * DDIM + k0 + c0);
        As[0][c0+0][r0]=ra0.x; As[0][c0+1][r0]=ra0.y; As[0][c0+2][r0]=ra0.z; As[0][c0+3][r0]=ra0.w;
        As[0][c0+0][r1]=ra1.x; As[0][c0+1][r1]=ra1.y; As[0][c0+2][r1]=ra1.z; As[0][c0+3][r1]=ra1.w;
        Bs[0][c0+0][r0]=rb0.x; Bs[0][c0+1][r0]=rb0.y; Bs[0][c0+2][r0]=rb0.z; Bs[0][c0+3][r0]=rb0.w;
        Bs[0][c0+0][r1]=rb1.x; Bs[0][c0+1][r1]=rb1.y; Bs[0][c0+2][r1]=rb1.z; Bs[0][c0+3][r1]=rb1.w;
    }
    __syncthreads();

    const int kIters = DDIM / BK;  // 32
    for (int kt = 0; kt < kIters; kt++) {
        const int cur = kt & 1;
        if (kt + 1 < kIters) {
            const int k0 = (kt + 1) * BK;
            ra0 = *(const float4*)(Abase + (size_t)r0 * DDIM + k0 + c0);
            ra1 = *(const float4*)(Abase + (size_t)r1 * DDIM + k0 + c0);
            rb0 = *(const float4*)(Bbase + (size_t)r0 * DDIM + k0 + c0);
            rb1 = *(const float4*)(Bbase + (size_t)r1 * DDIM + k0 + c0);
        }
        #pragma unroll
        for (int k = 0; k < BK; k++) {
            float a[8], bb[8];
            *(float4*)&a[0]  = *(const float4*)&As[cur][k][ty * 8];
            *(float4*)&a[4]  = *(const float4*)&As[cur][k][ty * 8 + 4];
            *(float4*)&bb[0] = *(const float4*)&Bs[cur][k][tx * 8];
            *(float4*)&bb[4] = *(const float4*)&Bs[cur][k][tx * 8 + 4];
            #pragma unroll
            for (int i = 0; i < 8; i++)
                #pragma unroll
                for (int j = 0; j < 8; j++)
                    acc[i][j] = fmaf(a[i], bb[j], acc[i][j]);
        }
        if (kt + 1 < kIters) {
            const int nxt = cur ^ 1;
            As[nxt][c0+0][r0]=ra0.x; As[nxt][c0+1][r0]=ra0.y; As[nxt][c0+2][r0]=ra0.z; As[nxt][c0+3][r0]=ra0.w;
            As[nxt][c0+0][r1]=ra1.x; As[nxt][c0+1][r1]=ra1.y; As[nxt][c0+2][r1]=ra1.z; As[nxt][c0+3][r1]=ra1.w;
            Bs[nxt][c0+0][r0]=rb0.x; Bs[nxt][c0+1][r0]=rb0.y; Bs[nxt][c0+2][r0]=rb0.z; Bs[nxt][c0+3][r0]=rb0.w;
            Bs[nxt][c0+0][r1]=rb1.x; Bs[nxt][c0+1][r1]=rb1.y; Bs[nxt][c0+2][r1]=rb1.z; Bs[nxt][c0+3][r1]=rb1.w;
            __syncthreads();
        }
    }

    // ---------------- epilogue: masked reductions ----------------
    int lj[8];
    #pragma unroll
    for (int j = 0; j < 8; j++) lj[j] = sLabJ[tx * 8 + j];

    float cmin[8], cmax[8];
    #pragma unroll
    for (int j = 0; j < 8; j++) { cmin[j] = 1e30f; cmax[j] = -1e30f; }

    const int rowT = rowBase + ty * 8;   // this thread's global row range base
    const int colT = colBase + tx * 8;   // this thread's global col range base

    #pragma unroll
    for (int i = 0; i < 8; i++) {
        const int gi = rowT + i;
        const int li = sLabI[ty * 8 + i];
        float rmin = 1e30f, rmax = -1e30f;
        #pragma unroll
        for (int j = 0; j < 8; j++) {
            const float g    = acc[i][j];
            const bool  same = (li == lj[j]);
            const bool  self = (gi == colT + j);
            if (same) {
                if (!self) {
                    rmin = fminf(rmin, g);
                    cmin[j] = fminf(cmin[j], g);
                }
            } else {
                rmax = fmaxf(rmax, g);
                cmax[j] = fmaxf(cmax[j], g);
            }
        }
        // reduce row value across the 16 tx-threads (contiguous lanes)
        #pragma unroll
        for (int o = 8; o; o >>= 1) {
            rmin = fminf(rmin, __shfl_xor_sync(0xffffffffu, rmin, o));
            rmax = fmaxf(rmax, __shfl_xor_sync(0xffffffffu, rmax, o));
        }
        if (tx == 0) {
            if (rmin <  1e29f) atomicMin(&g_minposKey[gi], fenc(rmin));
            if (rmax > -1e29f) atomicMax(&g_maxnegKey[gi], fenc(rmax));
        }
    }

    // column reductions across ty (cross-warp -> via smem)
    __syncthreads();
    #pragma unroll
    for (int j = 0; j < 8; j++) {
        sColMin[ty][tx * 8 + j] = cmin[j];
        sColMax[ty][tx * 8 + j] = cmax[j];
    }
    __syncthreads();
    {
        const int c     = tid & 127;
        const bool doMax = (tid >= 128);
        float v = doMax ? -1e30f : 1e30f;
        #pragma unroll
        for (int t = 0; t < 16; t++)
            v = doMax ? fmaxf(v, sColMax[t][c]) : fminf(v, sColMin[t][c]);
        const int gc = colBase + c;
        if (doMax) { if (v > -1e29f) atomicMax(&g_maxnegKey[gc], fenc(v)); }
        else       { if (v <  1e29f) atomicMin(&g_minposKey[gc], fenc(v)); }
    }
}

// ---------------- kernel 4: final loss reduction --------------------------
__global__ void loss_kernel(float* __restrict__ out) {
    const int tid = threadIdx.x;  // 256 threads, 1 block
    float s = 0.0f;
    for (int r = tid; r < NROWS; r += 256) {
        const unsigned kp = g_minposKey[r];
        const unsigned kn = g_maxnegKey[r];
        if (kp == MINPOS_INIT || kn == MAXNEG_INIT) continue;  // no pos / no neg -> 0
        const float minpos = fdec(kp);
        const float maxneg = fdec(kn);
        const float l = maxneg - minpos + MARGIN;
        if (l > 0.0f) s += l;
    }
    __shared__ float red[256];
    red[tid] = s;
    __syncthreads();
    #pragma unroll
    for (int st = 128; st; st >>= 1) {
        if (tid < st) red[tid] += red[tid + st];
        __syncthreads();
    }
    if (tid == 0) out[0] = red[0] / (float)NROWS;
}

// ---------------- launch ---------------------------------------------------
extern "C" void kernel_launch(void* const* d_in, const int* in_sizes, int n_in,
                              void* d_out, int out_size) {
    const float* emb   = (const float*)d_in[0];
    const int*   lab32 = (const int*)d_in[1];
    float*       out   = (float*)d_out;

    detect_labels_kernel<<<1, 256>>>(lab32);
    init_kernel<<<(NROWS + 255) / 256, 256>>>(lab32);
    normalize_kernel<<<NROWS, 128>>>(emb);
    gram_kernel<<<NTRI, 256>>>();
    loss_kernel<<<1, 256>>>(out);
}